// round 13
// baseline (speedup 1.0000x reference)
#include <cuda_runtime.h>
#include <cuda_bf16.h>
#include <cuda_fp16.h>

#define N_NODES  500000
#define N_EDGES  2500000
#define N_GRAPHS 1024
#define NPT      8   // nodes per thread in the pool kernel

// ---------------- scratch (device globals: no allocation allowed) ----------
__device__ __align__(16) float   g_aggx[(size_t)N_NODES * 4];   // {sum_x, sum_y, deg, pad}
__device__ __align__(32) __half2 g_h1h[(size_t)N_NODES * 8];    // relu(conv1) fp16 (16 feats)
__device__ __align__(32) __half2 g_aggh[(size_t)N_NODES * 8];   // fp16 aggregation of h1
__device__ float g_deg[N_NODES];                                // compact degree
__device__ __align__(16) float g_sums[(size_t)N_GRAPHS * 32];   // per-graph feature sums
__device__ float g_cnt[N_GRAPHS];                               // per-graph node counts

// ---------------- vectorized global reductions -----------------------------
__device__ __forceinline__ void red4f(float* p, float a, float b, float c, float d) {
    asm volatile("red.global.add.v4.f32 [%0], {%1, %2, %3, %4};"
                 :: "l"(p), "f"(a), "f"(b), "f"(c), "f"(d) : "memory");
}
__device__ __forceinline__ void red1f(float* p, float a) {
    asm volatile("red.global.add.f32 [%0], %1;" :: "l"(p), "f"(a) : "memory");
}
__device__ __forceinline__ void red4h2(__half2* p, unsigned r0, unsigned r1,
                                       unsigned r2, unsigned r3) {
    asm volatile("red.global.add.noftz.v4.f16x2 [%0], {%1, %2, %3, %4};"
                 :: "l"(p), "r"(r0), "r"(r1), "r"(r2), "r"(r3) : "memory");
}

// ---------------- kernel 1: init self-loop contributions + zero pool bufs --
__global__ void k_init(const float2* __restrict__ x) {
    int i = blockIdx.x * blockDim.x + threadIdx.x;
    if (i < N_GRAPHS) {
        g_cnt[i] = 0.0f;
        float4* s = (float4*)(g_sums + (size_t)i * 32);
#pragma unroll
        for (int q = 0; q < 8; q++) s[q] = make_float4(0.f, 0.f, 0.f, 0.f);
    }
    if (i >= N_NODES) return;
    float2 xi = __ldg(&x[i]);
    ((float4*)g_aggx)[i] = make_float4(xi.x, xi.y, 1.0f, 0.0f);  // self loop, deg=1
}

// ---------------- kernel 2: layer-1 edge scatter (pre-linear) --------------
__global__ void k_edge1(const float2* __restrict__ x, const int* __restrict__ ei) {
    int e = blockIdx.x * blockDim.x + threadIdx.x;
    if (e >= N_EDGES) return;
    int s = __ldg(&ei[e]);
    int d = __ldg(&ei[N_EDGES + e]);
    float2 xs = __ldg(&x[s]);
    red4f(g_aggx + (size_t)d * 4, xs.x, xs.y, 1.0f, 0.0f);
}

// ---------------- kernel 3: h1 = relu(W1^T*aggx + deg*b1) -> f16 x2 bufs ---
__global__ void k_node1(const float* __restrict__ W1, const float* __restrict__ b1) {
    __shared__ float sW[48];   // W1 (2x16) then b1 (16)
    if (threadIdx.x < 32)      sW[threadIdx.x] = W1[threadIdx.x];
    else if (threadIdx.x < 48) sW[threadIdx.x] = b1[threadIdx.x - 32];
    __syncthreads();
    int i = blockIdx.x * blockDim.x + threadIdx.x;
    if (i >= N_NODES) return;
    float4 a = ((const float4*)g_aggx)[i];
    float h[16];
#pragma unroll
    for (int j = 0; j < 16; j++)
        h[j] = fmaxf(fmaf(a.x, sW[j], fmaf(a.y, sW[16 + j], a.z * sW[32 + j])), 0.0f);

    __half2 hp[8];
#pragma unroll
    for (int q = 0; q < 8; q++) hp[q] = __floats2half2_rn(h[2*q], h[2*q+1]);
    float4 v0 = ((float4*)hp)[0];
    float4 v1 = ((float4*)hp)[1];

    float4* ph = (float4*)(g_h1h  + (size_t)i * 8);   // pure copy for edge gather
    float4* pa = (float4*)(g_aggh + (size_t)i * 8);   // self-loop seed (atomics add here)
    ph[0] = v0; ph[1] = v1;
    pa[0] = v0; pa[1] = v1;

    g_deg[i] = a.z;   // compact degree for the pool kernel
}

// ---------------- kernel 4: layer-2 edge scatter (f16 gather + f16 atomics)
__global__ void k_edge2(const int* __restrict__ ei) {
    int e = blockIdx.x * blockDim.x + threadIdx.x;
    if (e >= N_EDGES) return;
    int s = __ldg(&ei[e]);
    int d = __ldg(&ei[N_EDGES + e]);
    const uint4* hp = (const uint4*)(g_h1h + (size_t)s * 8);
    uint4 r0 = __ldg(hp + 0);
    uint4 r1 = __ldg(hp + 1);
    __half2* p = g_aggh + (size_t)d * 8;
    red4h2(p + 0, r0.x, r0.y, r0.z, r0.w);
    red4h2(p + 4, r1.x, r1.y, r1.z, r1.w);
}

// ---------------- kernel 5: h2 = relu(W2^T*aggh + deg*b2); pooled sums -----
__device__ __forceinline__ void flush_graph(int g, const float* acc, float cc) {
    float* ps = g_sums + (size_t)g * 32;
#pragma unroll
    for (int q = 0; q < 8; q++)
        red4f(ps + 4*q, acc[4*q], acc[4*q+1], acc[4*q+2], acc[4*q+3]);
    red1f(&g_cnt[g], cc);
}

__global__ void __launch_bounds__(256) k_pool(const int* __restrict__ batch,
                       const float* __restrict__ W2, const float* __restrict__ b2) {
    __shared__ float sW[512 + 32];  // W2 (16x32) then b2 (32)
    for (int t = threadIdx.x; t < 544; t += blockDim.x)
        sW[t] = (t < 512) ? W2[t] : b2[t - 512];
    __syncthreads();

    int t = blockIdx.x * blockDim.x + threadIdx.x;
    int base = t * NPT;
    if (base >= N_NODES) return;
    int end = min(base + NPT, N_NODES);

    // prefetch group ids (contiguous, cheap)
    int gid[NPT];
#pragma unroll
    for (int q = 0; q < NPT; q++)
        gid[q] = (base + q < N_NODES) ? __ldg(&batch[base + q]) : -1;

    float acc[32];
    float cc = 0.0f;
    int curg = -1;

#pragma unroll 1
    for (int i = base; i < end; i++) {
        int g = gid[i - base];
        float deg = g_deg[i];

        const float4* pr = (const float4*)(g_aggh + (size_t)i * 8);
        float4 v0 = pr[0];
        float4 v1 = pr[1];
        const __half2* q0 = (const __half2*)&v0;
        const __half2* q1 = (const __half2*)&v1;
        float hv[16];
#pragma unroll
        for (int q = 0; q < 4; q++) {
            float2 f0 = __half22float2(q0[q]);
            float2 f1 = __half22float2(q1[q]);
            hv[2*q]   = f0.x; hv[2*q+1]   = f0.y;
            hv[8+2*q] = f1.x; hv[8+2*q+1] = f1.y;
        }

        float out[32];
#pragma unroll
        for (int k = 0; k < 32; k++) out[k] = deg * sW[512 + k];
#pragma unroll
        for (int j = 0; j < 16; j++) {
            float hj = hv[j];
            const float4* wrow = (const float4*)(sW + j * 32);
#pragma unroll
            for (int q = 0; q < 8; q++) {
                float4 w = wrow[q];
                out[4*q+0] = fmaf(hj, w.x, out[4*q+0]);
                out[4*q+1] = fmaf(hj, w.y, out[4*q+1]);
                out[4*q+2] = fmaf(hj, w.z, out[4*q+2]);
                out[4*q+3] = fmaf(hj, w.w, out[4*q+3]);
            }
        }
#pragma unroll
        for (int k = 0; k < 32; k++) out[k] = fmaxf(out[k], 0.0f);

        if (g != curg) {
            if (curg >= 0) flush_graph(curg, acc, cc);
#pragma unroll
            for (int k = 0; k < 32; k++) acc[k] = out[k];
            cc = 1.0f;
            curg = g;
        } else {
#pragma unroll
            for (int k = 0; k < 32; k++) acc[k] += out[k];
            cc += 1.0f;
        }
    }
    if (curg >= 0) flush_graph(curg, acc, cc);
}

// ---------------- kernel 6: final MLP over 1024 graphs ---------------------
__global__ void k_final(const float* __restrict__ Wf1, const float* __restrict__ bf1,
                        const float* __restrict__ Wf2, const float* __restrict__ bf2,
                        float* __restrict__ out) {
    int g = blockIdx.x * blockDim.x + threadIdx.x;
    if (g >= N_GRAPHS) return;
    float inv = 1.0f / fmaxf(g_cnt[g], 1.0f);
    float p[32];
#pragma unroll
    for (int k = 0; k < 32; k++) p[k] = g_sums[(size_t)g * 32 + k] * inv;

    float o = __ldg(&bf2[0]);
#pragma unroll
    for (int j = 0; j < 16; j++) {
        float s = __ldg(&bf1[j]);
#pragma unroll
        for (int k = 0; k < 32; k++)
            s = fmaf(p[k], __ldg(&Wf1[k * 16 + j]), s);
        o = fmaf(fmaxf(s, 0.0f), __ldg(&Wf2[j]), o);
    }
    out[g] = o;
}

// ---------------- launch ---------------------------------------------------
extern "C" void kernel_launch(void* const* d_in, const int* in_sizes, int n_in,
                              void* d_out, int out_size) {
    const float2* x     = (const float2*)d_in[0];
    const int*    ei    = (const int*)   d_in[1];
    const int*    batch = (const int*)   d_in[2];
    const float*  W1    = (const float*) d_in[3];
    const float*  b1    = (const float*) d_in[4];
    const float*  W2    = (const float*) d_in[5];
    const float*  b2    = (const float*) d_in[6];
    const float*  Wf1   = (const float*) d_in[7];
    const float*  bf1   = (const float*) d_in[8];
    const float*  Wf2   = (const float*) d_in[9];
    const float*  bf2   = (const float*) d_in[10];
    float* out = (float*)d_out;

    const int TB = 256;
    k_init <<<(N_NODES + TB - 1) / TB, TB>>>(x);
    k_edge1<<<(N_EDGES + TB - 1) / TB, TB>>>(x, ei);
    k_node1<<<(N_NODES + TB - 1) / TB, TB>>>(W1, b1);
    k_edge2<<<(N_EDGES + TB - 1) / TB, TB>>>(ei);
    int pool_threads = (N_NODES + NPT - 1) / NPT;
    k_pool <<<(pool_threads + TB - 1) / TB, TB>>>(batch, W2, b2);
    k_final<<<(N_GRAPHS + TB - 1) / TB, TB>>>(Wf1, bf1, Wf2, bf2, out);
}

// round 15
// speedup vs baseline: 6.0721x; 6.0721x over previous
#include <cuda_runtime.h>
#include <cuda_bf16.h>
#include <cuda_fp16.h>

#define N_NODES  500000
#define N_EDGES  2500000
#define N_GRAPHS 1024
#define NPT      8   // nodes per thread in the pool kernel

// ---------------- scratch (device globals: no allocation allowed) ----------
__device__ __align__(16) float   g_aggx[(size_t)N_NODES * 4];   // {sum_x, sum_y, deg, pad}
__device__ __align__(32) __half2 g_h1h[(size_t)N_NODES * 8];    // relu(conv1) fp16 (16 feats)
__device__ __align__(32) __half2 g_aggh[(size_t)N_NODES * 8];   // fp16 aggregation of h1
__device__ float g_deg[N_NODES];                                // compact degree
__device__ __align__(16) float g_sums[(size_t)N_GRAPHS * 32];   // per-graph feature sums
__device__ float g_cnt[N_GRAPHS];                               // per-graph node counts

// ---------------- vectorized global reductions -----------------------------
__device__ __forceinline__ void red4f(float* p, float a, float b, float c, float d) {
    asm volatile("red.global.add.v4.f32 [%0], {%1, %2, %3, %4};"
                 :: "l"(p), "f"(a), "f"(b), "f"(c), "f"(d) : "memory");
}
__device__ __forceinline__ void red1f(float* p, float a) {
    asm volatile("red.global.add.f32 [%0], %1;" :: "l"(p), "f"(a) : "memory");
}
__device__ __forceinline__ void red4h2(__half2* p, unsigned r0, unsigned r1,
                                       unsigned r2, unsigned r3) {
    asm volatile("red.global.add.noftz.v4.f16x2 [%0], {%1, %2, %3, %4};"
                 :: "l"(p), "r"(r0), "r"(r1), "r"(r2), "r"(r3) : "memory");
}

// ---------------- kernel 1: init self-loop contributions + zero pool bufs --
__global__ void k_init(const float2* __restrict__ x) {
    int i = blockIdx.x * blockDim.x + threadIdx.x;
    if (i < N_GRAPHS) {
        g_cnt[i] = 0.0f;
        float4* s = (float4*)(g_sums + (size_t)i * 32);
#pragma unroll
        for (int q = 0; q < 8; q++) s[q] = make_float4(0.f, 0.f, 0.f, 0.f);
    }
    if (i >= N_NODES) return;
    float2 xi = __ldg(&x[i]);
    ((float4*)g_aggx)[i] = make_float4(xi.x, xi.y, 1.0f, 0.0f);  // self loop, deg=1
}

// ---------------- kernel 2: layer-1 edge scatter (pre-linear) --------------
__global__ void k_edge1(const float2* __restrict__ x, const int* __restrict__ ei) {
    int e = blockIdx.x * blockDim.x + threadIdx.x;
    if (e >= N_EDGES) return;
    int s = __ldg(&ei[e]);
    int d = __ldg(&ei[N_EDGES + e]);
    float2 xs = __ldg(&x[s]);
    red4f(g_aggx + (size_t)d * 4, xs.x, xs.y, 1.0f, 0.0f);
}

// ---------------- kernel 3: h1 = relu(W1^T*aggx + deg*b1) -> f16 x2 bufs ---
__global__ void k_node1(const float* __restrict__ W1, const float* __restrict__ b1) {
    __shared__ float sW[48];   // W1 (2x16) then b1 (16)
    if (threadIdx.x < 32)      sW[threadIdx.x] = W1[threadIdx.x];
    else if (threadIdx.x < 48) sW[threadIdx.x] = b1[threadIdx.x - 32];
    __syncthreads();
    int i = blockIdx.x * blockDim.x + threadIdx.x;
    if (i >= N_NODES) return;
    float4 a = ((const float4*)g_aggx)[i];
    float h[16];
#pragma unroll
    for (int j = 0; j < 16; j++)
        h[j] = fmaxf(fmaf(a.x, sW[j], fmaf(a.y, sW[16 + j], a.z * sW[32 + j])), 0.0f);

    __half2 hp[8];
#pragma unroll
    for (int q = 0; q < 8; q++) hp[q] = __floats2half2_rn(h[2*q], h[2*q+1]);
    float4 v0 = ((float4*)hp)[0];
    float4 v1 = ((float4*)hp)[1];

    float4* ph = (float4*)(g_h1h  + (size_t)i * 8);   // pure copy for edge gather
    float4* pa = (float4*)(g_aggh + (size_t)i * 8);   // self-loop seed (atomics add here)
    ph[0] = v0; ph[1] = v1;
    pa[0] = v0; pa[1] = v1;

    g_deg[i] = a.z;   // compact degree for the pool kernel
}

// ---------------- kernel 4: layer-2 edge scatter (f16 gather + f16 atomics)
__global__ void k_edge2(const int* __restrict__ ei) {
    int e = blockIdx.x * blockDim.x + threadIdx.x;
    if (e >= N_EDGES) return;
    int s = __ldg(&ei[e]);
    int d = __ldg(&ei[N_EDGES + e]);
    const uint4* hp = (const uint4*)(g_h1h + (size_t)s * 8);
    uint4 r0 = __ldg(hp + 0);
    uint4 r1 = __ldg(hp + 1);
    __half2* p = g_aggh + (size_t)d * 8;
    red4h2(p + 0, r0.x, r0.y, r0.z, r0.w);
    red4h2(p + 4, r1.x, r1.y, r1.z, r1.w);
}

// ---------------- kernel 5: h2 = relu(W2^T*aggh + deg*b2); pooled sums -----
__device__ __forceinline__ void flush_graph(int g, const float* acc, float cc) {
    float* ps = g_sums + (size_t)g * 32;
#pragma unroll
    for (int q = 0; q < 8; q++)
        red4f(ps + 4*q, acc[4*q], acc[4*q+1], acc[4*q+2], acc[4*q+3]);
    red1f(&g_cnt[g], cc);
}

__global__ void __launch_bounds__(256) k_pool(const int* __restrict__ batch,
                       const float* __restrict__ W2, const float* __restrict__ b2) {
    __shared__ float sW[512 + 32];  // W2 (16x32) then b2 (32)
    for (int t = threadIdx.x; t < 544; t += blockDim.x)
        sW[t] = (t < 512) ? W2[t] : b2[t - 512];
    __syncthreads();

    int t = blockIdx.x * blockDim.x + threadIdx.x;
    int base = t * NPT;
    if (base >= N_NODES) return;
    int end = min(base + NPT, N_NODES);

    float acc[32];
    float cc = 0.0f;
    int curg = -1;

#pragma unroll 1
    for (int i = base; i < end; i++) {
        int g = __ldg(&batch[i]);
        float deg = g_deg[i];

        const float4* pr = (const float4*)(g_aggh + (size_t)i * 8);
        float4 v0 = pr[0];
        float4 v1 = pr[1];
        const __half2* q0 = (const __half2*)&v0;
        const __half2* q1 = (const __half2*)&v1;
        float hv[16];
#pragma unroll
        for (int q = 0; q < 4; q++) {
            float2 f0 = __half22float2(q0[q]);
            float2 f1 = __half22float2(q1[q]);
            hv[2*q]     = f0.x; hv[2*q+1]     = f0.y;
            hv[8+2*q]   = f1.x; hv[8+2*q+1]   = f1.y;
        }

        float out[32];
#pragma unroll
        for (int k = 0; k < 32; k++) out[k] = deg * sW[512 + k];
#pragma unroll
        for (int j = 0; j < 16; j++) {
            float hj = hv[j];
            const float4* wrow = (const float4*)(sW + j * 32);
#pragma unroll
            for (int q = 0; q < 8; q++) {
                float4 w = wrow[q];
                out[4*q+0] = fmaf(hj, w.x, out[4*q+0]);
                out[4*q+1] = fmaf(hj, w.y, out[4*q+1]);
                out[4*q+2] = fmaf(hj, w.z, out[4*q+2]);
                out[4*q+3] = fmaf(hj, w.w, out[4*q+3]);
            }
        }
#pragma unroll
        for (int k = 0; k < 32; k++) out[k] = fmaxf(out[k], 0.0f);

        if (g != curg) {
            if (curg >= 0) flush_graph(curg, acc, cc);
#pragma unroll
            for (int k = 0; k < 32; k++) acc[k] = out[k];
            cc = 1.0f;
            curg = g;
        } else {
#pragma unroll
            for (int k = 0; k < 32; k++) acc[k] += out[k];
            cc += 1.0f;
        }
    }
    if (curg >= 0) flush_graph(curg, acc, cc);
}

// ---------------- kernel 6: final MLP over 1024 graphs ---------------------
__global__ void k_final(const float* __restrict__ Wf1, const float* __restrict__ bf1,
                        const float* __restrict__ Wf2, const float* __restrict__ bf2,
                        float* __restrict__ out) {
    int g = blockIdx.x * blockDim.x + threadIdx.x;
    if (g >= N_GRAPHS) return;
    float inv = 1.0f / fmaxf(g_cnt[g], 1.0f);
    float p[32];
#pragma unroll
    for (int k = 0; k < 32; k++) p[k] = g_sums[(size_t)g * 32 + k] * inv;

    float o = __ldg(&bf2[0]);
#pragma unroll
    for (int j = 0; j < 16; j++) {
        float s = __ldg(&bf1[j]);
#pragma unroll
        for (int k = 0; k < 32; k++)
            s = fmaf(p[k], __ldg(&Wf1[k * 16 + j]), s);
        o = fmaf(fmaxf(s, 0.0f), __ldg(&Wf2[j]), o);
    }
    out[g] = o;
}

// ---------------- launch ---------------------------------------------------
extern "C" void kernel_launch(void* const* d_in, const int* in_sizes, int n_in,
                              void* d_out, int out_size) {
    const float2* x     = (const float2*)d_in[0];
    const int*    ei    = (const int*)   d_in[1];
    const int*    batch = (const int*)   d_in[2];
    const float*  W1    = (const float*) d_in[3];
    const float*  b1    = (const float*) d_in[4];
    const float*  W2    = (const float*) d_in[5];
    const float*  b2    = (const float*) d_in[6];
    const float*  Wf1   = (const float*) d_in[7];
    const float*  bf1   = (const float*) d_in[8];
    const float*  Wf2   = (const float*) d_in[9];
    const float*  bf2   = (const float*) d_in[10];
    float* out = (float*)d_out;

    const int TB = 256;
    k_init <<<(N_NODES + TB - 1) / TB, TB>>>(x);
    k_edge1<<<(N_EDGES + TB - 1) / TB, TB>>>(x, ei);
    k_node1<<<(N_NODES + TB - 1) / TB, TB>>>(W1, b1);
    k_edge2<<<(N_EDGES + TB - 1) / TB, TB>>>(ei);
    int pool_threads = (N_NODES + NPT - 1) / NPT;
    k_pool <<<(pool_threads + TB - 1) / TB, TB>>>(batch, W2, b2);
    k_final<<<(N_GRAPHS + TB - 1) / TB, TB>>>(Wf1, bf1, Wf2, bf2, out);
}